// round 3
// baseline (speedup 1.0000x reference)
#include <cuda_runtime.h>
#include <cstdint>
#include <cstddef>

// Problem constants
#define BB 64
#define TT 512
#define II 1024
#define HH 1024

// ---------------- scratch (device globals; no cudaMalloc allowed) ----------------
__device__ float g_xw[(size_t)BB * TT * HH];      // 128 MiB: xw = x@W^T + bW
__device__ float g_state[2][(size_t)BB * HH];     // ping-pong recurrent state
__device__ unsigned g_bar_count;
__device__ unsigned g_bar_gen;

// ---------------- grid-wide software barrier (all CTAs resident) ----------------
__device__ __forceinline__ void grid_sync(unsigned nctas) {
    __syncthreads();
    if (threadIdx.x == 0) {
        unsigned g = *((volatile unsigned*)&g_bar_gen);
        __threadfence();
        unsigned a = atomicAdd(&g_bar_count, 1u);
        if (a == nctas - 1u) {
            g_bar_count = 0u;
            __threadfence();
            *((volatile unsigned*)&g_bar_gen) = g + 1u;
        } else {
            while (*((volatile unsigned*)&g_bar_gen) == g) { __nanosleep(64); }
        }
        __threadfence();
    }
    __syncthreads();
}

// ---------------- fast accurate tanh (MUFU EX2 + RCP, ~1e-7 rel err) ----------------
__device__ __forceinline__ float fast_tanh(float x) {
    float ax = fabsf(x);
    float e  = __expf(-2.0f * ax);
    float r  = __fdividef(1.0f - e, 1.0f + e);
    return copysignf(r, x);
}

// =====================================================================
// Kernel 1: xw[m][n] = sum_k x[m][k] * W[n][k] + bW[n]
// M = B*T = 32768, N = H = 1024, K = I = 1024
// 64x64 tile, BK=16, 256 threads, 4x4 microtile.
// =====================================================================
#define BM 64
#define BN 64
#define BK 16

__global__ __launch_bounds__(256) void gemm1_kernel(
    const float* __restrict__ x, const float* __restrict__ W,
    const float* __restrict__ bW)
{
    __shared__ float As[BK][BM];   // [k][m]
    __shared__ float Bs[BK][BN];   // [k][n]

    const int tid = threadIdx.x;
    const int tx = tid & 15;         // 0..15 -> n micro
    const int ty = tid >> 4;         // 0..15 -> m micro
    const int m_blk = blockIdx.y * BM;
    const int n_blk = blockIdx.x * BN;

    const int lr  = tid >> 2;        // 0..63  row within tile for loads
    const int lkq = tid & 3;         // 0..3   k-quad for loads

    float acc[4][4];
#pragma unroll
    for (int i = 0; i < 4; ++i)
#pragma unroll
        for (int j = 0; j < 4; ++j) acc[i][j] = 0.0f;

    for (int kk = 0; kk < II; kk += BK) {
        // load A tile (64 rows x 16 k) and W tile (64 rows x 16 k), transpose into smem
        float4 a4 = *(const float4*)&x[(size_t)(m_blk + lr) * II + kk + lkq * 4];
        float4 b4 = *(const float4*)&W[(size_t)(n_blk + lr) * II + kk + lkq * 4];
        __syncthreads();
        As[lkq * 4 + 0][lr] = a4.x; As[lkq * 4 + 1][lr] = a4.y;
        As[lkq * 4 + 2][lr] = a4.z; As[lkq * 4 + 3][lr] = a4.w;
        Bs[lkq * 4 + 0][lr] = b4.x; Bs[lkq * 4 + 1][lr] = b4.y;
        Bs[lkq * 4 + 2][lr] = b4.z; Bs[lkq * 4 + 3][lr] = b4.w;
        __syncthreads();
#pragma unroll
        for (int k = 0; k < BK; ++k) {
            float4 av = *(const float4*)&As[k][ty * 4];
            float4 bv = *(const float4*)&Bs[k][tx * 4];
            acc[0][0] = fmaf(av.x, bv.x, acc[0][0]);
            acc[0][1] = fmaf(av.x, bv.y, acc[0][1]);
            acc[0][2] = fmaf(av.x, bv.z, acc[0][2]);
            acc[0][3] = fmaf(av.x, bv.w, acc[0][3]);
            acc[1][0] = fmaf(av.y, bv.x, acc[1][0]);
            acc[1][1] = fmaf(av.y, bv.y, acc[1][1]);
            acc[1][2] = fmaf(av.y, bv.z, acc[1][2]);
            acc[1][3] = fmaf(av.y, bv.w, acc[1][3]);
            acc[2][0] = fmaf(av.z, bv.x, acc[2][0]);
            acc[2][1] = fmaf(av.z, bv.y, acc[2][1]);
            acc[2][2] = fmaf(av.z, bv.z, acc[2][2]);
            acc[2][3] = fmaf(av.z, bv.w, acc[2][3]);
            acc[3][0] = fmaf(av.w, bv.x, acc[3][0]);
            acc[3][1] = fmaf(av.w, bv.y, acc[3][1]);
            acc[3][2] = fmaf(av.w, bv.z, acc[3][2]);
            acc[3][3] = fmaf(av.w, bv.w, acc[3][3]);
        }
    }

    float4 bw4 = *(const float4*)&bW[n_blk + tx * 4];
#pragma unroll
    for (int i = 0; i < 4; ++i) {
        float4 c;
        c.x = acc[i][0] + bw4.x; c.y = acc[i][1] + bw4.y;
        c.z = acc[i][2] + bw4.z; c.w = acc[i][3] + bw4.w;
        *(float4*)&g_xw[(size_t)(m_blk + ty * 4 + i) * HH + n_blk + tx * 4] = c;
    }
}

// =====================================================================
// Kernel 2: persistent scan.
// 128 CTAs = 4 b-tiles (16 batch each) x 32 n-tiles (32 cols of U each).
// U slice (32x1024 fp32, row stride 1028 for bank-conflict-free float4
// reads) lives in SMEM for all 512 steps. Per step:
//   Phase A: h3s[bi][k] = tanh(xw[b,t,k] + state[b,k]) into smem
//            (nt==0 CTA also streams h3 to out1 / out2)
//   Phase B: t_next[b, n] = bU[n] + sum_k h3s[b][k] * Us[n][k]
//   one grid barrier.
// =====================================================================
#define SCAN_CTAS 128
#define U_STRIDE 1028   // 1028 % 32 == 4 -> conflict-free float4 col reads
#define SMEM_SCAN ((32 * U_STRIDE + 16 * 1024) * 4)   // 197120 bytes

__global__ __launch_bounds__(256, 1) void scan_kernel(
    const float* __restrict__ U, const float* __restrict__ bU,
    float* __restrict__ out1, float* __restrict__ out2)
{
    extern __shared__ float smem[];
    float* Us  = smem;                    // [32][U_STRIDE]
    float* h3s = smem + 32 * U_STRIDE;    // [16][1024]

    const int tid = threadIdx.x;
    const int bt = blockIdx.x >> 5;       // 0..3
    const int nt = blockIdx.x & 31;       // 0..31
    const int b0 = bt * 16;
    const int n0 = nt * 32;

    // load U slice into SMEM once (rows n0..n0+31)
    for (int idx = tid; idx < 32 * 256; idx += 256) {
        int r = idx >> 8, k4 = idx & 255;
        float4 u = *(const float4*)&U[(size_t)(n0 + r) * HH + k4 * 4];
        *(float4*)&Us[r * U_STRIDE + k4 * 4] = u;
    }

    const int n_loc = tid & 31;           // 0..31 (column within slice)
    const int bg    = tid >> 5;           // 0..7
    const int bi0   = bg * 2;             // thread owns batch rows bi0, bi0+1
    const float bu  = bU[n0 + n_loc];

    // zero initial state (t0 = 0); disjoint coverage across CTAs/threads
    g_state[0][(size_t)(b0 + bi0)     * HH + n0 + n_loc] = 0.0f;
    g_state[0][(size_t)(b0 + bi0 + 1) * HH + n0 + n_loc] = 0.0f;
    __threadfence();
    grid_sync(SCAN_CTAS);

    for (int t = 0; t < TT; ++t) {
        const float* scur  = g_state[t & 1];
        float*       snext = g_state[(t & 1) ^ 1];

        // ---- Phase A: h3 = tanh(xw_t + state) ----
        for (int e = tid; e < 16 * 256; e += 256) {
            int bi = e >> 8, k4 = e & 255;
            int b = b0 + bi;
            size_t off = ((size_t)b * TT + t) * HH + k4 * 4;
            float4 xv = *(const float4*)&g_xw[off];
            float4 sv = *(const float4*)&scur[(size_t)b * HH + k4 * 4];
            float4 h;
            h.x = fast_tanh(xv.x + sv.x);
            h.y = fast_tanh(xv.y + sv.y);
            h.z = fast_tanh(xv.z + sv.z);
            h.w = fast_tanh(xv.w + sv.w);
            *(float4*)&h3s[bi * 1024 + k4 * 4] = h;
            if (nt == 0) {
                *(float4*)&out1[off] = h;
                if (t == TT - 1)
                    *(float4*)&out2[(size_t)b * HH + k4 * 4] = h;
            }
        }
        __syncthreads();

        // ---- Phase B: t_next = h3 @ U^T + bU  (this CTA's 16x32 tile) ----
        float acc0 = bu, acc1 = bu;
        const float* urow = &Us[n_loc * U_STRIDE];
        const float* har  = &h3s[bi0 * 1024];
        const float* hbr  = &h3s[(bi0 + 1) * 1024];
#pragma unroll 4
        for (int k4 = 0; k4 < 256; ++k4) {
            float4 u  = *(const float4*)&urow[k4 * 4];
            float4 ha = *(const float4*)&har[k4 * 4];
            float4 hb = *(const float4*)&hbr[k4 * 4];
            acc0 = fmaf(u.x, ha.x, acc0);
            acc0 = fmaf(u.y, ha.y, acc0);
            acc0 = fmaf(u.z, ha.z, acc0);
            acc0 = fmaf(u.w, ha.w, acc0);
            acc1 = fmaf(u.x, hb.x, acc1);
            acc1 = fmaf(u.y, hb.y, acc1);
            acc1 = fmaf(u.z, hb.z, acc1);
            acc1 = fmaf(u.w, hb.w, acc1);
        }
        snext[(size_t)(b0 + bi0)     * HH + n0 + n_loc] = acc0;
        snext[(size_t)(b0 + bi0 + 1) * HH + n0 + n_loc] = acc1;
        __threadfence();
        grid_sync(SCAN_CTAS);
    }
}

// =====================================================================
// launch
// =====================================================================
extern "C" void kernel_launch(void* const* d_in, const int* in_sizes, int n_in,
                              void* d_out, int out_size)
{
    const float* x  = (const float*)d_in[0];
    const float* W  = (const float*)d_in[1];
    const float* bW = (const float*)d_in[2];
    const float* U  = (const float*)d_in[3];
    const float* bU = (const float*)d_in[4];

    float* out1 = (float*)d_out;
    float* out2 = out1 + (size_t)BB * TT * HH;

    cudaFuncSetAttribute(scan_kernel,
                         cudaFuncAttributeMaxDynamicSharedMemorySize, SMEM_SCAN);

    dim3 g1(HH / BN, (BB * TT) / BM);   // (16, 512)
    gemm1_kernel<<<g1, 256>>>(x, W, bW);
    scan_kernel<<<SCAN_CTAS, 256, SMEM_SCAN>>>(U, bU, out1, out2);
}

// round 4
// speedup vs baseline: 1.2822x; 1.2822x over previous
#include <cuda_runtime.h>
#include <cstdint>
#include <cstddef>

#define BB 64
#define TT 512
#define II 1024
#define HH 1024

typedef unsigned long long ull;

// ---------------- scratch (device globals; no cudaMalloc allowed) ----------------
__device__ float g_xw[(size_t)BB * TT * HH];      // 128 MiB: xw = x@W^T + bW
__device__ float g_state[2][(size_t)BB * HH];     // ping-pong recurrent state
__device__ unsigned g_count;                      // monotonic barrier counter

// ---------------- f32x2 helpers ----------------
__device__ __forceinline__ void ffma2(ull &d, ull a, ull b) {
    asm("fma.rn.f32x2 %0, %1, %2, %0;" : "+l"(d) : "l"(a), "l"(b));
}
__device__ __forceinline__ float lohi_sum(ull v) {
    float lo, hi;
    asm("mov.b64 {%0, %1}, %2;" : "=f"(lo), "=f"(hi) : "l"(v));
    return lo + hi;
}

// ---------------- fast accurate tanh (2x MUFU, ~1e-7 rel err) ----------------
__device__ __forceinline__ float fast_tanh(float x) {
    float ax = fabsf(x);
    float e  = __expf(-2.0f * ax);
    float r  = __fdividef(1.0f - e, 1.0f + e);
    return copysignf(r, x);
}

// ---------------- grid barrier: monotonic counter, no reset race ----------------
__device__ __forceinline__ void grid_bar(unsigned phase) {
    __syncthreads();
    if (threadIdx.x == 0) {
        __threadfence();                       // release prior global writes
        atomicAdd(&g_count, 1u);
        const unsigned target = phase * 128u;
        while (*(volatile unsigned*)&g_count < target) {}
        __threadfence();                       // acquire other CTAs' writes
    }
    __syncthreads();
}

// =====================================================================
// Kernel 1: xw = x @ W^T + bW.  M=32768, N=1024, K=1024.
// CTA tile 64x64, BK=32, 256 threads. FFMA2 over k-parity.
// Warp tile 16m x 32n; lane (lm=l&3, ln=l>>2) owns 4m x 4n
// (m strided by 4, n strided by 8) -> all LDS.128 are 1 wavefront.
// =====================================================================
#define G_STR 36   // row stride (floats): 16B-group = m mod 8 -> conflict-free

__global__ __launch_bounds__(256, 2) void gemm1_kernel(
    const float* __restrict__ x, const float* __restrict__ W,
    const float* __restrict__ bW)
{
    if (blockIdx.x == 0 && blockIdx.y == 0 && threadIdx.x == 0) g_count = 0u;

    __shared__ float As[64 * G_STR];
    __shared__ float Bs[64 * G_STR];

    const int tid = threadIdx.x;
    const int m_blk = blockIdx.y * 64, n_blk = blockIdx.x * 64;
    const int w = tid >> 5, l = tid & 31;
    const int wm = (w & 3) * 16, wn = (w >> 2) * 32;
    const int lm = l & 3, ln = l >> 2;
    const int lrow = tid >> 2, lcol = (tid & 3) * 4;

    ull acc[4][4];
#pragma unroll
    for (int i = 0; i < 4; ++i)
#pragma unroll
        for (int j = 0; j < 4; ++j) acc[i][j] = 0ULL;

    for (int kk = 0; kk < II; kk += 32) {
        const float* xp = &x[(size_t)(m_blk + lrow) * II + kk + lcol];
        const float* wp = &W[(size_t)(n_blk + lrow) * II + kk + lcol];
        float4 xa = *(const float4*)xp;
        float4 xb = *(const float4*)(xp + 16);
        float4 wa = *(const float4*)wp;
        float4 wb = *(const float4*)(wp + 16);
        __syncthreads();
        *(float4*)&As[lrow * G_STR + lcol]      = xa;
        *(float4*)&As[lrow * G_STR + lcol + 16] = xb;
        *(float4*)&Bs[lrow * G_STR + lcol]      = wa;
        *(float4*)&Bs[lrow * G_STR + lcol + 16] = wb;
        __syncthreads();
#pragma unroll
        for (int kq = 0; kq < 8; ++kq) {
            ulonglong2 a[4], b[4];
#pragma unroll
            for (int i = 0; i < 4; ++i)
                a[i] = *(const ulonglong2*)&As[(wm + lm + 4 * i) * G_STR + kq * 4];
#pragma unroll
            for (int j = 0; j < 4; ++j)
                b[j] = *(const ulonglong2*)&Bs[(wn + ln + 8 * j) * G_STR + kq * 4];
#pragma unroll
            for (int i = 0; i < 4; ++i)
#pragma unroll
                for (int j = 0; j < 4; ++j) {
                    ffma2(acc[i][j], a[i].x, b[j].x);
                    ffma2(acc[i][j], a[i].y, b[j].y);
                }
        }
    }

    float bwv[4];
#pragma unroll
    for (int j = 0; j < 4; ++j) bwv[j] = bW[n_blk + wn + ln + 8 * j];
#pragma unroll
    for (int i = 0; i < 4; ++i) {
        const size_t row = (size_t)(m_blk + wm + lm + 4 * i) * HH + n_blk + wn + ln;
#pragma unroll
        for (int j = 0; j < 4; ++j)
            g_xw[row + 8 * j] = lohi_sum(acc[i][j]) + bwv[j];
    }
}

// =====================================================================
// Kernel 2: persistent scan. 128 CTAs = 4 b-tiles x 32 n-tiles.
// U slice (32 rows) in SMEM for all 512 steps.
// Phase A: h3 = tanh(xw_t + state) into SMEM; each CTA streams its own
//          32-wide k-slice of h3 to out1 (balanced across nt).
// Phase B: 8 warps = 4 k-quarters x 2 b-halves; lane owns 2b x 4n
//          f32x2 accs; k-partials reduced through SMEM.
// =====================================================================
#define U_STR 1028   // 16B-group = n mod 8
#define H_STR 1032   // 16B-group = 2b mod 8
#define RED_OFF (32 * U_STR + 16 * H_STR)
#define SMEM_SCAN ((RED_OFF + 2048) * 4)   // 205824 bytes

__global__ __launch_bounds__(256, 1) void scan_kernel(
    const float* __restrict__ U, const float* __restrict__ bU,
    float* __restrict__ out1, float* __restrict__ out2)
{
    extern __shared__ float smem[];
    float* Us  = smem;               // [32][U_STR]
    float* h3s = smem + 32 * U_STR;  // [16][H_STR]
    float* red = smem + RED_OFF;     // [4][16][32]

    const int tid = threadIdx.x;
    const int bt = blockIdx.x >> 5, nt = blockIdx.x & 31;
    const int b0 = bt * 16, n0 = nt * 32;

    // load U slice (rows n0..n0+31) once
    for (int i = tid; i < 32 * 256; i += 256) {
        int r = i >> 8, c = (i & 255) * 4;
        *(float4*)&Us[r * U_STR + c] = *(const float4*)&U[(size_t)(n0 + r) * HH + c];
    }

    const int w = tid >> 5, l = tid & 31;
    const int wk = w >> 1;            // k-quarter 0..3
    const int wb = (w & 1) * 8;       // b half base
    const int lb = l & 3, ln = l >> 2;
    const int k0 = wk * 256;

    const int k4 = tid * 4;                              // phase-A column (const per thread)
    const bool wr = (k4 >= n0) && (k4 < n0 + 32);        // this thread streams out1

    const float bu0 = bU[n0 + (tid & 31)];               // for reduce outputs o=tid, o+256
    const float bu1 = bU[n0 + ((tid + 256) & 31)];

    for (int t = 0; t < TT; ++t) {
        if (t) grid_bar((unsigned)t);
        const float* scur = g_state[t & 1];

        // ---- Phase A ----
#pragma unroll 4
        for (int bi = 0; bi < 16; ++bi) {
            const int b = b0 + bi;
            const size_t off = ((size_t)b * TT + t) * HH + k4;
            float4 v = *(const float4*)&g_xw[off];
            if (t) {
                float4 s = *(const float4*)&scur[(size_t)b * HH + k4];
                v.x += s.x; v.y += s.y; v.z += s.z; v.w += s.w;
            }
            float4 h;
            h.x = fast_tanh(v.x); h.y = fast_tanh(v.y);
            h.z = fast_tanh(v.z); h.w = fast_tanh(v.w);
            *(float4*)&h3s[bi * H_STR + k4] = h;
            if (wr) {
                *(float4*)&out1[off] = h;
                if (t == TT - 1) *(float4*)&out2[(size_t)b * HH + k4] = h;
            }
        }
        __syncthreads();

        // ---- Phase B: partial sums over this warp's k-quarter ----
        ull acc[2][4];
#pragma unroll
        for (int i = 0; i < 2; ++i)
#pragma unroll
            for (int j = 0; j < 4; ++j) acc[i][j] = 0ULL;

#pragma unroll 4
        for (int kq = 0; kq < 64; ++kq) {
            const int k = k0 + kq * 4;
            ulonglong2 hv0 = *(const ulonglong2*)&h3s[(wb + lb) * H_STR + k];
            ulonglong2 hv1 = *(const ulonglong2*)&h3s[(wb + lb + 4) * H_STR + k];
            ulonglong2 uv[4];
#pragma unroll
            for (int j = 0; j < 4; ++j)
                uv[j] = *(const ulonglong2*)&Us[(ln + 8 * j) * U_STR + k];
#pragma unroll
            for (int j = 0; j < 4; ++j) {
                ffma2(acc[0][j], hv0.x, uv[j].x);
                ffma2(acc[0][j], hv0.y, uv[j].y);
                ffma2(acc[1][j], hv1.x, uv[j].x);
                ffma2(acc[1][j], hv1.y, uv[j].y);
            }
        }
#pragma unroll
        for (int i = 0; i < 2; ++i)
#pragma unroll
            for (int j = 0; j < 4; ++j)
                red[wk * 512 + (wb + lb + 4 * i) * 32 + ln + 8 * j] = lohi_sum(acc[i][j]);
        __syncthreads();

        // ---- reduce 4 k-partials, add bias, store next state ----
        float* snext = g_state[(t + 1) & 1];
        {
            const int o0 = tid, o1 = tid + 256;
            float s0 = red[o0] + red[512 + o0] + red[1024 + o0] + red[1536 + o0] + bu0;
            float s1 = red[o1] + red[512 + o1] + red[1024 + o1] + red[1536 + o1] + bu1;
            snext[(size_t)(b0 + (o0 >> 5)) * HH + n0 + (o0 & 31)] = s0;
            snext[(size_t)(b0 + (o1 >> 5)) * HH + n0 + (o1 & 31)] = s1;
        }
    }
}

// =====================================================================
// launch
// =====================================================================
extern "C" void kernel_launch(void* const* d_in, const int* in_sizes, int n_in,
                              void* d_out, int out_size)
{
    const float* x  = (const float*)d_in[0];
    const float* W  = (const float*)d_in[1];
    const float* bW = (const float*)d_in[2];
    const float* U  = (const float*)d_in[3];
    const float* bU = (const float*)d_in[4];

    float* out1 = (float*)d_out;
    float* out2 = out1 + (size_t)BB * TT * HH;

    cudaFuncSetAttribute(scan_kernel,
                         cudaFuncAttributeMaxDynamicSharedMemorySize, SMEM_SCAN);

    dim3 g1(HH / 64, (BB * TT) / 64);   // (16, 512)
    gemm1_kernel<<<g1, 256>>>(x, W, bW);
    scan_kernel<<<128, 256, SMEM_SCAN>>>(U, bU, out1, out2);
}

// round 6
// speedup vs baseline: 1.9266x; 1.5026x over previous
#include <cuda_runtime.h>
#include <cstdint>
#include <cstddef>

#define BB 64
#define TT 512
#define II 1024
#define HH 1024

typedef unsigned long long ull;

// ---------------- scratch (device globals; no cudaMalloc allowed) ----------------
__device__ float g_xw[(size_t)BB * TT * HH];      // 128 MiB: xw = x@W^T + bW
__device__ float g_state[2][(size_t)BB * HH];     // ping-pong recurrent state
__device__ unsigned g_count;                      // monotonic barrier counter

// ---------------- f32x2 helpers ----------------
__device__ __forceinline__ void ffma2(ull &d, ull a, ull b) {
    asm("fma.rn.f32x2 %0, %1, %2, %0;" : "+l"(d) : "l"(a), "l"(b));
}
__device__ __forceinline__ float lohi_sum(ull v) {
    float lo, hi;
    asm("mov.b64 {%0, %1}, %2;" : "=f"(lo), "=f"(hi) : "l"(v));
    return lo + hi;
}

// ---------------- hw tanh (single MUFU.TANH, max err ~2e-5) ----------------
__device__ __forceinline__ float hw_tanh(float x) {
    float r;
    asm("tanh.approx.f32 %0, %1;" : "=f"(r) : "f"(x));
    return r;
}

// ---------------- grid barrier: monotonic counter ----------------
__device__ __forceinline__ void grid_bar(unsigned phase) {
    __syncthreads();
    if (threadIdx.x == 0) {
        __threadfence();                       // release (cumulative)
        atomicAdd(&g_count, 1u);
        const unsigned target = phase * 128u;
        while (*(volatile unsigned*)&g_count < target) {}
        __threadfence();                       // acquire
    }
    __syncthreads();
}

// =====================================================================
// Kernel 1: xw = x @ W^T + bW.  M=32768, N=1024, K=1024.
// CTA 64x64, BK=32, 256 threads, FFMA2, double-buffered smem.
// =====================================================================
#define G_STR 36   // row stride (floats): 16B-group = row mod 8 -> conflict-free

__global__ __launch_bounds__(256, 2) void gemm1_kernel(
    const float* __restrict__ x, const float* __restrict__ W,
    const float* __restrict__ bW)
{
    if (blockIdx.x == 0 && blockIdx.y == 0 && threadIdx.x == 0) g_count = 0u;

    __shared__ float As[2][64 * G_STR];
    __shared__ float Bs[2][64 * G_STR];

    const int tid = threadIdx.x;
    const int m_blk = blockIdx.y * 64, n_blk = blockIdx.x * 64;
    const int w = tid >> 5, l = tid & 31;
    const int wm = (w & 3) * 16, wn = (w >> 2) * 32;
    const int lm = l & 3, ln = l >> 2;
    const int lrow = tid >> 2, lcol = (tid & 3) * 4;

    const float* xp = &x[(size_t)(m_blk + lrow) * II + lcol];
    const float* wp = &W[(size_t)(n_blk + lrow) * II + lcol];

    ull acc[4][4];
#pragma unroll
    for (int i = 0; i < 4; ++i)
#pragma unroll
        for (int j = 0; j < 4; ++j) acc[i][j] = 0ULL;

    // preload stage 0
    {
        float4 xa = *(const float4*)xp;
        float4 xb = *(const float4*)(xp + 16);
        float4 wa = *(const float4*)wp;
        float4 wb = *(const float4*)(wp + 16);
        *(float4*)&As[0][lrow * G_STR + lcol]      = xa;
        *(float4*)&As[0][lrow * G_STR + lcol + 16] = xb;
        *(float4*)&Bs[0][lrow * G_STR + lcol]      = wa;
        *(float4*)&Bs[0][lrow * G_STR + lcol + 16] = wb;
    }
    __syncthreads();

    for (int it = 0; it < II / 32; ++it) {
        const int cur = it & 1, nxt = cur ^ 1;
        float4 xa, xb, wa, wb;
        const bool more = (it + 1) < II / 32;
        if (more) {
            const int kk = (it + 1) * 32;
            xa = *(const float4*)(xp + kk);
            xb = *(const float4*)(xp + kk + 16);
            wa = *(const float4*)(wp + kk);
            wb = *(const float4*)(wp + kk + 16);
        }
#pragma unroll
        for (int kq = 0; kq < 8; ++kq) {
            ulonglong2 a[4], b[4];
#pragma unroll
            for (int i = 0; i < 4; ++i)
                a[i] = *(const ulonglong2*)&As[cur][(wm + lm + 4 * i) * G_STR + kq * 4];
#pragma unroll
            for (int j = 0; j < 4; ++j)
                b[j] = *(const ulonglong2*)&Bs[cur][(wn + ln + 8 * j) * G_STR + kq * 4];
#pragma unroll
            for (int i = 0; i < 4; ++i)
#pragma unroll
                for (int j = 0; j < 4; ++j) {
                    ffma2(acc[i][j], a[i].x, b[j].x);
                    ffma2(acc[i][j], a[i].y, b[j].y);
                }
        }
        if (more) {
            *(float4*)&As[nxt][lrow * G_STR + lcol]      = xa;
            *(float4*)&As[nxt][lrow * G_STR + lcol + 16] = xb;
            *(float4*)&Bs[nxt][lrow * G_STR + lcol]      = wa;
            *(float4*)&Bs[nxt][lrow * G_STR + lcol + 16] = wb;
        }
        __syncthreads();
    }

    float bwv[4];
#pragma unroll
    for (int j = 0; j < 4; ++j) bwv[j] = bW[n_blk + wn + ln + 8 * j];
#pragma unroll
    for (int i = 0; i < 4; ++i) {
        const size_t row = (size_t)(m_blk + wm + lm + 4 * i) * HH + n_blk + wn + ln;
#pragma unroll
        for (int j = 0; j < 4; ++j)
            g_xw[row + 8 * j] = lohi_sum(acc[i][j]) + bwv[j];
    }
}

// =====================================================================
// Kernel 2: persistent scan. 128 CTAs = 4 b-tiles x 32 n-tiles,
// 512 threads (16 warps, 4/SMSP).
// Phase A: h3 = tanh(xw_t + state); xw prefetched to regs BEFORE the
//          grid barrier. Each CTA streams its own 32-wide k-slice to out1.
// Phase B: 16 warps = 8 k-eighths x 2 b-halves; lane owns 2b x 4n
//          f32x2 accs; 8 k-partials reduced through SMEM.
// =====================================================================
#define U_STR 1028   // 16B-group = n mod 8
#define H_STR 1032   // 16B-group = 2b mod 8
#define RED_OFF (32 * U_STR + 16 * H_STR)
#define SMEM_SCAN ((RED_OFF + 8 * 512) * 4)   // 214016 bytes

__global__ __launch_bounds__(512, 1) void scan_kernel(
    const float* __restrict__ U, const float* __restrict__ bU,
    float* __restrict__ out1, float* __restrict__ out2)
{
    extern __shared__ float smem[];
    float* Us  = smem;               // [32][U_STR]
    float* h3s = smem + 32 * U_STR;  // [16][H_STR]
    float* red = smem + RED_OFF;     // [8][512]

    const int tid = threadIdx.x;
    const int bt = blockIdx.x >> 5, nt = blockIdx.x & 31;
    const int b0 = bt * 16, n0 = nt * 32;

    // load U slice (rows n0..n0+31) once
    for (int i = tid; i < 32 * 256; i += 512) {
        int r = i >> 8, c = (i & 255) * 4;
        *(float4*)&Us[r * U_STR + c] = *(const float4*)&U[(size_t)(n0 + r) * HH + c];
    }

    // Phase-A mapping: thread covers 8 rows (r2, r2+2, ... r2+14), one col k4
    const int r2 = tid >> 8;               // 0 or 1
    const int k4 = (tid & 255) * 4;
    const bool wr = (k4 >= n0) && (k4 < n0 + 32);   // streams out1 for this col

    // Phase-B mapping
    const int w = tid >> 5, l = tid & 31;
    const int wk = w >> 1;                 // k-eighth 0..7
    const int wb = (w & 1) * 8;            // b half
    const int lb = l & 3, ln = l >> 2;
    const int k0 = wk * 128;

    const float bu = bU[n0 + (tid & 31)];  // for reduce output o = tid

    for (int t = 0; t < TT; ++t) {
        // ---- prefetch xw (independent of barrier) ----
        float4 pf[8];
#pragma unroll
        for (int i = 0; i < 8; ++i) {
            const int b = b0 + r2 + 2 * i;
            pf[i] = *(const float4*)&g_xw[((size_t)b * TT + t) * HH + k4];
        }

        if (t) grid_bar((unsigned)t);
        const float* scur = g_state[t & 1];

        // ---- Phase A ----
#pragma unroll
        for (int i = 0; i < 8; ++i) {
            const int bi = r2 + 2 * i;
            const int b = b0 + bi;
            float4 v = pf[i];
            if (t) {
                float4 s = *(const float4*)&scur[(size_t)b * HH + k4];
                v.x += s.x; v.y += s.y; v.z += s.z; v.w += s.w;
            }
            float4 h;
            h.x = hw_tanh(v.x); h.y = hw_tanh(v.y);
            h.z = hw_tanh(v.z); h.w = hw_tanh(v.w);
            *(float4*)&h3s[bi * H_STR + k4] = h;
            if (wr) {
                *(float4*)&out1[((size_t)b * TT + t) * HH + k4] = h;
                if (t == TT - 1) *(float4*)&out2[(size_t)b * HH + k4] = h;
            }
        }
        __syncthreads();

        // ---- Phase B: partials over this warp's 128-wide k-eighth ----
        ull acc[2][4];
#pragma unroll
        for (int i = 0; i < 2; ++i)
#pragma unroll
            for (int j = 0; j < 4; ++j) acc[i][j] = 0ULL;

#pragma unroll 4
        for (int kq = 0; kq < 32; ++kq) {
            const int k = k0 + kq * 4;
            ulonglong2 hv0 = *(const ulonglong2*)&h3s[(wb + lb) * H_STR + k];
            ulonglong2 hv1 = *(const ulonglong2*)&h3s[(wb + lb + 4) * H_STR + k];
            ulonglong2 uv[4];
#pragma unroll
            for (int j = 0; j < 4; ++j)
                uv[j] = *(const ulonglong2*)&Us[(ln + 8 * j) * U_STR + k];
#pragma unroll
            for (int j = 0; j < 4; ++j) {
                ffma2(acc[0][j], hv0.x, uv[j].x);
                ffma2(acc[0][j], hv0.y, uv[j].y);
                ffma2(acc[1][j], hv1.x, uv[j].x);
                ffma2(acc[1][j], hv1.y, uv[j].y);
            }
        }
#pragma unroll
        for (int i = 0; i < 2; ++i)
#pragma unroll
            for (int j = 0; j < 4; ++j)
                red[wk * 512 + (wb + lb + 4 * i) * 32 + ln + 8 * j] = lohi_sum(acc[i][j]);
        __syncthreads();

        // ---- reduce 8 k-partials, add bias, store next state ----
        float* snext = g_state[(t + 1) & 1];
        {
            const int o = tid;
            float s = bu;
#pragma unroll
            for (int p = 0; p < 8; ++p) s += red[p * 512 + o];
            snext[(size_t)(b0 + (o >> 5)) * HH + n0 + (o & 31)] = s;
        }
    }
}

// =====================================================================
// launch
// =====================================================================
extern "C" void kernel_launch(void* const* d_in, const int* in_sizes, int n_in,
                              void* d_out, int out_size)
{
    const float* x  = (const float*)d_in[0];
    const float* W  = (const float*)d_in[1];
    const float* bW = (const float*)d_in[2];
    const float* U  = (const float*)d_in[3];
    const float* bU = (const float*)d_in[4];

    float* out1 = (float*)d_out;
    float* out2 = out1 + (size_t)BB * TT * HH;

    cudaFuncSetAttribute(scan_kernel,
                         cudaFuncAttributeMaxDynamicSharedMemorySize, SMEM_SCAN);

    dim3 g1(HH / 64, (BB * TT) / 64);   // (16, 512)
    gemm1_kernel<<<g1, 256>>>(x, W, bW);
    scan_kernel<<<128, 512, SMEM_SCAN>>>(U, bU, out1, out2);
}

// round 7
// speedup vs baseline: 2.2774x; 1.1821x over previous
#include <cuda_runtime.h>
#include <cstdint>
#include <cstddef>

#define BB 64
#define TT 512
#define II 1024
#define HH 1024

typedef unsigned long long ull;

// ---------------- scratch (device globals; no cudaMalloc allowed) ----------------
__device__ float g_xw[(size_t)BB * TT * HH];   // 128 MiB: xw = x@W^T + bW
__device__ float g_h3[2][(size_t)BB * HH];     // ping-pong h3 exchange
__device__ unsigned g_cnt[128];                // per-b-group counters (slot bt*32)

// ---------------- f32x2 helpers ----------------
__device__ __forceinline__ void ffma2(ull &d, ull a, ull b) {
    asm("fma.rn.f32x2 %0, %1, %2, %0;" : "+l"(d) : "l"(a), "l"(b));
}
__device__ __forceinline__ float lohi_sum(ull v) {
    float lo, hi;
    asm("mov.b64 {%0, %1}, %2;" : "=f"(lo), "=f"(hi) : "l"(v));
    return lo + hi;
}
__device__ __forceinline__ float hw_tanh(float x) {
    float r;
    asm("tanh.approx.f32 %0, %1;" : "=f"(r) : "f"(x));
    return r;
}

// =====================================================================
// Kernel 1: xw = x @ W^T + bW.  (unchanged from R5, + counter reset)
// =====================================================================
#define G_STR 36

__global__ __launch_bounds__(256, 2) void gemm1_kernel(
    const float* __restrict__ x, const float* __restrict__ W,
    const float* __restrict__ bW)
{
    if (blockIdx.x == 0 && blockIdx.y == 0 && threadIdx.x < 128)
        g_cnt[threadIdx.x] = 0u;

    __shared__ float As[2][64 * G_STR];
    __shared__ float Bs[2][64 * G_STR];

    const int tid = threadIdx.x;
    const int m_blk = blockIdx.y * 64, n_blk = blockIdx.x * 64;
    const int w = tid >> 5, l = tid & 31;
    const int wm = (w & 3) * 16, wn = (w >> 2) * 32;
    const int lm = l & 3, ln = l >> 2;
    const int lrow = tid >> 2, lcol = (tid & 3) * 4;

    const float* xp = &x[(size_t)(m_blk + lrow) * II + lcol];
    const float* wp = &W[(size_t)(n_blk + lrow) * II + lcol];

    ull acc[4][4];
#pragma unroll
    for (int i = 0; i < 4; ++i)
#pragma unroll
        for (int j = 0; j < 4; ++j) acc[i][j] = 0ULL;

    {
        float4 xa = *(const float4*)xp;
        float4 xb = *(const float4*)(xp + 16);
        float4 wa = *(const float4*)wp;
        float4 wb = *(const float4*)(wp + 16);
        *(float4*)&As[0][lrow * G_STR + lcol]      = xa;
        *(float4*)&As[0][lrow * G_STR + lcol + 16] = xb;
        *(float4*)&Bs[0][lrow * G_STR + lcol]      = wa;
        *(float4*)&Bs[0][lrow * G_STR + lcol + 16] = wb;
    }
    __syncthreads();

    for (int it = 0; it < II / 32; ++it) {
        const int cur = it & 1, nxt = cur ^ 1;
        float4 xa, xb, wa, wb;
        const bool more = (it + 1) < II / 32;
        if (more) {
            const int kk = (it + 1) * 32;
            xa = *(const float4*)(xp + kk);
            xb = *(const float4*)(xp + kk + 16);
            wa = *(const float4*)(wp + kk);
            wb = *(const float4*)(wp + kk + 16);
        }
#pragma unroll
        for (int kq = 0; kq < 8; ++kq) {
            ulonglong2 a[4], b[4];
#pragma unroll
            for (int i = 0; i < 4; ++i)
                a[i] = *(const ulonglong2*)&As[cur][(wm + lm + 4 * i) * G_STR + kq * 4];
#pragma unroll
            for (int j = 0; j < 4; ++j)
                b[j] = *(const ulonglong2*)&Bs[cur][(wn + ln + 8 * j) * G_STR + kq * 4];
#pragma unroll
            for (int i = 0; i < 4; ++i)
#pragma unroll
                for (int j = 0; j < 4; ++j) {
                    ffma2(acc[i][j], a[i].x, b[j].x);
                    ffma2(acc[i][j], a[i].y, b[j].y);
                }
        }
        if (more) {
            *(float4*)&As[nxt][lrow * G_STR + lcol]      = xa;
            *(float4*)&As[nxt][lrow * G_STR + lcol + 16] = xb;
            *(float4*)&Bs[nxt][lrow * G_STR + lcol]      = wa;
            *(float4*)&Bs[nxt][lrow * G_STR + lcol + 16] = wb;
        }
        __syncthreads();
    }

    float bwv[4];
#pragma unroll
    for (int j = 0; j < 4; ++j) bwv[j] = bW[n_blk + wn + ln + 8 * j];
#pragma unroll
    for (int i = 0; i < 4; ++i) {
        const size_t row = (size_t)(m_blk + wm + lm + 4 * i) * HH + n_blk + wn + ln;
#pragma unroll
        for (int j = 0; j < 4; ++j)
            g_xw[row + 8 * j] = lohi_sum(acc[i][j]) + bwv[j];
    }
}

// =====================================================================
// Kernel 2: persistent scan, h3-exchange formulation.
// 128 CTAs = 4 b-groups x 32 n-tiles, 512 threads.
// Owner CTA (bt,nt) produces h3[t+1] for its 16b x 32n outputs:
//   t_next = h3[t] @ U^T + bU  (full k via smem patches, 16-warp split)
//   h3[t+1] = tanh(t_next + xw[t+1])   -> g_h3 ping-pong + out1
// One 32-CTA barrier per step. No CTA-wide sync before Phase B:
// each warp loads exactly the 8b x 128k h3 patch it consumes.
// =====================================================================
#define U_STR 1028                 // 16B-group = n mod 8
#define H_STR 1032                 // 16B-group = 2b mod 8
#define RED_OFF (32 * U_STR + 16 * H_STR)
#define R_STR 40                   // red row stride: bank = (8*row + col) % 32
#define SMEM_SCAN ((RED_OFF + 8 * 16 * R_STR) * 4)   // 218112 bytes

__global__ __launch_bounds__(512, 1) void scan_kernel(
    const float* __restrict__ U, const float* __restrict__ bU,
    float* __restrict__ out1, float* __restrict__ out2)
{
    extern __shared__ float smem[];
    float* Us  = smem;               // [32][U_STR]  U rows n0..n0+31
    float* h3s = smem + 32 * U_STR;  // [16][H_STR]  h3 patch cache
    float* red = smem + RED_OFF;     // [8][16][R_STR]

    const int tid = threadIdx.x;
    const int bt = blockIdx.x >> 5, nt = blockIdx.x & 31;
    const int b0 = bt * 16, n0 = nt * 32;
    unsigned* cnt = &g_cnt[bt * 32];

    // load U slice once
    for (int i = tid; i < 32 * 256; i += 512) {
        int r = i >> 8, c = (i & 255) * 4;
        *(float4*)&Us[r * U_STR + c] = *(const float4*)&U[(size_t)(n0 + r) * HH + c];
    }

    // owner/output mapping: one output element per thread
    const int bi = tid >> 5;              // 0..15 batch row
    const int nl = tid & 31;              // 0..31 column
    const float bu = bU[n0 + nl];
    const size_t orow = (size_t)(b0 + bi) * TT * HH + n0 + nl;  // out1 row base
    const size_t hrow = (size_t)(b0 + bi) * HH + n0 + nl;       // g_h3 index

    // Phase-B mapping: 16 warps = 8 k-eighths x 2 b-halves
    const int w = tid >> 5, l = tid & 31;
    const int wk = w >> 1;                // k-eighth 0..7
    const int wb = (w & 1) * 8;           // b half base
    const int lb = l & 3, ln = l >> 2;
    const int k0 = wk * 128;

    // ---- bootstrap: h3[0] = tanh(xw[0]) ----
    {
        float h = hw_tanh(g_xw[orow]);
        g_h3[0][hrow] = h;
        out1[orow] = h;
    }
    __syncthreads();
    if (tid == 0) { __threadfence(); atomicAdd(cnt, 1u); }

    for (int t = 0; t < TT - 1; ++t) {
        // ---- wait: h3[t] published by all 32 CTAs of this b-group ----
        if (tid == 0) {
            const unsigned target = 32u * (unsigned)(t + 1);
            while (*(volatile unsigned*)cnt < target) {}
            __threadfence();
        }
        __syncthreads();

        // prefetch xw[t+1] for own output element
        const float xwv = g_xw[orow + (size_t)(t + 1) * HH];

        // ---- load own h3 patch (rows wb..wb+7, cols k0..k0+127) ----
        const float* hsrc = &g_h3[t & 1][(size_t)b0 * HH];
#pragma unroll
        for (int r = 0; r < 8; ++r) {
            float4 hv = *(const float4*)&hsrc[(size_t)(wb + r) * HH + k0 + l * 4];
            *(float4*)&h3s[(wb + r) * H_STR + k0 + l * 4] = hv;
        }
        __syncwarp();

        // ---- Phase B: partials over this warp's 128-wide k-eighth ----
        ull acc[2][4];
#pragma unroll
        for (int i = 0; i < 2; ++i)
#pragma unroll
            for (int j = 0; j < 4; ++j) acc[i][j] = 0ULL;

#pragma unroll 4
        for (int kq = 0; kq < 32; ++kq) {
            const int k = k0 + kq * 4;
            ulonglong2 hv0 = *(const ulonglong2*)&h3s[(wb + lb) * H_STR + k];
            ulonglong2 hv1 = *(const ulonglong2*)&h3s[(wb + lb + 4) * H_STR + k];
            ulonglong2 uv[4];
#pragma unroll
            for (int j = 0; j < 4; ++j)
                uv[j] = *(const ulonglong2*)&Us[(ln + 8 * j) * U_STR + k];
#pragma unroll
            for (int j = 0; j < 4; ++j) {
                ffma2(acc[0][j], hv0.x, uv[j].x);
                ffma2(acc[0][j], hv0.y, uv[j].y);
                ffma2(acc[1][j], hv1.x, uv[j].x);
                ffma2(acc[1][j], hv1.y, uv[j].y);
            }
        }
#pragma unroll
        for (int i = 0; i < 2; ++i)
#pragma unroll
            for (int j = 0; j < 4; ++j)
                red[wk * (16 * R_STR) + (wb + lb + 4 * i) * R_STR + ln + 8 * j] =
                    lohi_sum(acc[i][j]);
        __syncthreads();

        // ---- reduce 8 partials, fuse bias + xw + tanh, publish h3[t+1] ----
        float s = bu;
#pragma unroll
        for (int p = 0; p < 8; ++p)
            s += red[p * (16 * R_STR) + bi * R_STR + nl];
        const float h = hw_tanh(s + xwv);
        g_h3[(t + 1) & 1][hrow] = h;
        out1[orow + (size_t)(t + 1) * HH] = h;
        if (t == TT - 2) out2[hrow] = h;
        __syncthreads();
        if (tid == 0) { __threadfence(); atomicAdd(cnt, 1u); }
    }
}

// =====================================================================
// launch
// =====================================================================
extern "C" void kernel_launch(void* const* d_in, const int* in_sizes, int n_in,
                              void* d_out, int out_size)
{
    const float* x  = (const float*)d_in[0];
    const float* W  = (const float*)d_in[1];
    const float* bW = (const float*)d_in[2];
    const float* U  = (const float*)d_in[3];
    const float* bU = (const float*)d_in[4];

    float* out1 = (float*)d_out;
    float* out2 = out1 + (size_t)BB * TT * HH;

    cudaFuncSetAttribute(scan_kernel,
                         cudaFuncAttributeMaxDynamicSharedMemorySize, SMEM_SCAN);

    dim3 g1(HH / 64, (BB * TT) / 64);   // (16, 512)
    gemm1_kernel<<<g1, 256>>>(x, W, bW);
    scan_kernel<<<128, 512, SMEM_SCAN>>>(U, bU, out1, out2);
}